// round 4
// baseline (speedup 1.0000x reference)
#include <cuda_runtime.h>

// ---------------------------------------------------------------------------
// stripe_post: column scans + 98-tap guided filter (r=49 module boxfilter,
// which is actually an asymmetric 98-tap window [i-48, i+49]) + diff scan.
// Shapes fixed: M=2048, N=4096, coarse rows MC=683, hX stride r=4.
// Outputs (concatenated): b_adpt, diff, diff_adpt, b  (each M*N f32).
// ---------------------------------------------------------------------------

static constexpr int M     = 2048;
static constexpr int NC    = 4096;
static constexpr int MCR   = 683;     // len(arange(2048)[::3])
static constexpr int SEG   = 128;
static constexpr int NSEG  = 16;      // 2048/128
static constexpr int NSEGC = 6;       // ceil(683/128)
static constexpr int PADL  = 48;
static constexpr int PADR  = 49;
static constexpr int TAPS  = 98;      // 2*r taps per axis
static constexpr int SMW   = NC + PADL + PADR; // 4193
static constexpr float BOXNORM = 1.0f / 9604.0f; // 1/(98*98)
static constexpr float CSC = 683.0f / 2048.0f;   // resize inv_scale

#define PLANE (M * NC)

// Scratch (static device globals: no allocation allowed)
__device__ float g_x [PLANE];
__device__ float g_t1[PLANE];
__device__ float g_t2[PLANE];
__device__ float g_t3[PLANE];
__device__ float g_t4[PLANE];
__device__ float g_Dc[MCR * NC];     // decay coarse cumsum
__device__ float g_pb[NSEG  * NC];   // b partial segment sums
__device__ float g_pd[NSEGC * NC];   // decay partial segment sums
__device__ float g_pD[NSEG  * NC];   // diff_adpt partial segment sums

__device__ __forceinline__ float softplusf(float x) {
    // matches jax.nn.softplus: max(x,0) + log1p(exp(-|x|))
    return fmaxf(x, 0.0f) + log1pf(expf(-fabsf(x)));
}

// ---------------------------------------------------------------------------
// Stage 0: decay coarse cumsum  (2-pass segmented column scan over 683 rows)
// ---------------------------------------------------------------------------
__global__ __launch_bounds__(256) void k_decay_part(
    const float* __restrict__ bneg, const float* __restrict__ dcol)
{
    int c   = blockIdx.x * 256 + threadIdx.x;
    int seg = blockIdx.y;
    int k0 = seg * SEG;
    int k1 = min(MCR, k0 + SEG);
    float s = 0.0f;
    for (int k = k0; k < k1; ++k) {
        int idx = k * NC + c;
        s += bneg[idx] * softplusf(dcol[idx]);
    }
    g_pd[seg * NC + c] = s;
}

__global__ __launch_bounds__(256) void k_decay_scan(
    const float* __restrict__ bneg, const float* __restrict__ dcol)
{
    int c   = blockIdx.x * 256 + threadIdx.x;
    int seg = blockIdx.y;
    float run = 0.0f;
    for (int s = 0; s < seg; ++s) run += g_pd[s * NC + c];
    int k0 = seg * SEG;
    int k1 = min(MCR, k0 + SEG);
    for (int k = k0; k < k1; ++k) {
        int idx = k * NC + c;
        run += bneg[idx] * softplusf(dcol[idx]);
        g_Dc[idx] = run;
    }
}

// ---------------------------------------------------------------------------
// Stage 1: b cumsum partials, then fused main scan:
//   b_full = cumsum(b*sp(w)) + decay_lerp*(1-fg)
//   b_adpt = b_full*fm + b_old*(1-fm)
//   x      = hX[4i] + b_adpt - recon_old
// ---------------------------------------------------------------------------
__global__ __launch_bounds__(256) void k_b_part(
    const float* __restrict__ b, const float* __restrict__ w)
{
    int c   = blockIdx.x * 256 + threadIdx.x;
    int seg = blockIdx.y;
    int i0 = seg * SEG;
    float s = 0.0f;
    for (int i = i0; i < i0 + SEG; ++i) {
        int idx = i * NC + c;
        s += b[idx] * softplusf(w[idx]);
    }
    g_pb[seg * NC + c] = s;
}

__global__ __launch_bounds__(256) void k_main(
    const float* __restrict__ b,     const float* __restrict__ w,
    const float* __restrict__ fg,    const float* __restrict__ hX,
    const float* __restrict__ recon, const float* __restrict__ fmask,
    const float* __restrict__ bold,
    float* __restrict__ o_badpt, float* __restrict__ o_b)
{
    int c   = blockIdx.x * 256 + threadIdx.x;
    int seg = blockIdx.y;
    float run = 0.0f;
    for (int s = 0; s < seg; ++s) run += g_pb[s * NC + c];
    int i0 = seg * SEG;

    // decay interpolation taps, tracked incrementally (coarse idx advances 0/1)
    float s0 = fminf(fmaxf((i0 + 0.5f) * CSC - 0.5f, 0.0f), 682.0f);
    int kcur = min((int)s0, 681);
    float D0 = g_Dc[kcur * NC + c];
    float D1 = g_Dc[(kcur + 1) * NC + c];

    for (int i = i0; i < i0 + SEG; ++i) {
        int idx = i * NC + c;
        run += b[idx] * softplusf(w[idx]);

        float sf = fminf(fmaxf((i + 0.5f) * CSC - 0.5f, 0.0f), 682.0f);
        int kk = min((int)sf, 681);
        if (kk != kcur) { kcur = kk; D0 = D1; D1 = g_Dc[(kk + 1) * NC + c]; }
        float f = sf - (float)kk;
        float decay = D0 + f * (D1 - D0);

        float bfull = run + decay * (1.0f - fg[idx]);
        float fmv = fmask[idx];
        float badpt = bfull * fmv + bold[idx] * (1.0f - fmv);
        float xv = hX[(i << 2) * NC + c] + badpt - recon[idx];

        o_b[idx]     = bfull;
        o_badpt[idx] = badpt;   // pre-subtraction; finalized in k_dscan
        g_x[idx]     = xv;
    }
}

// ---------------------------------------------------------------------------
// Horizontal 98-tap box (window [j-48, j+49], replicate pad).
// One block per row. Per-thread sliding chunk of 33 (coprime with 32 -> no
// smem bank conflicts); results staged in smem for coalesced global stores.
// ---------------------------------------------------------------------------
template <bool SQ>
__device__ __forceinline__ void hbox_pass(const float* smin, float* smout, int tid)
{
    int base = tid * 33;
    if (base >= NC) return;
    int cnt = min(33, NC - base);
    float s = 0.0f;
    #pragma unroll 14
    for (int u = 0; u < TAPS; ++u) {
        float v = smin[base + u];
        s += SQ ? v * v : v;
    }
    smout[base] = s;
    for (int j = 1; j < cnt; ++j) {
        float vn = smin[base + j + TAPS - 1];
        float vo = smin[base + j - 1];
        s += SQ ? (vn * vn - vo * vo) : (vn - vo);
        smout[base + j] = s;
    }
}

__device__ __forceinline__ void hbox_load_row(const float* __restrict__ rp,
                                              float* smin, int tid)
{
    for (int j = tid; j < NC; j += 128) smin[PADL + j] = rp[j];
    if (tid < PADL) smin[tid] = rp[0];
    if (tid >= 64 && tid < 64 + PADR) smin[NC + PADL + (tid - 64)] = rp[NC - 1];
}

// x -> row-sums of x (g_t1) and x^2 (g_t2)
__global__ __launch_bounds__(128) void k_hbox_x()
{
    __shared__ float smin[SMW];
    __shared__ float smout[NC];
    int row = blockIdx.x, tid = threadIdx.x;
    const float* rp = g_x + row * NC;
    hbox_load_row(rp, smin, tid);
    __syncthreads();
    hbox_pass<false>(smin, smout, tid);
    __syncthreads();
    for (int j = tid; j < NC; j += 128) g_t1[row * NC + j] = smout[j];
    __syncthreads();
    hbox_pass<true>(smin, smout, tid);
    __syncthreads();
    for (int j = tid; j < NC; j += 128) g_t2[row * NC + j] = smout[j];
}

// A (g_t3) -> g_t1 ; bb (g_t4) -> g_t2
__global__ __launch_bounds__(128) void k_hbox_ab()
{
    __shared__ float smin[SMW];
    __shared__ float smout[NC];
    int row = blockIdx.x, tid = threadIdx.x;
    hbox_load_row(g_t3 + row * NC, smin, tid);
    __syncthreads();
    hbox_pass<false>(smin, smout, tid);
    __syncthreads();
    // copy out A row-sums; concurrently reload smin with bb (no hazard)
    for (int j = tid; j < NC; j += 128) g_t1[row * NC + j] = smout[j];
    hbox_load_row(g_t4 + row * NC, smin, tid);
    __syncthreads();
    hbox_pass<false>(smin, smout, tid);
    __syncthreads();
    for (int j = tid; j < NC; j += 128) g_t2[row * NC + j] = smout[j];
}

// ---------------------------------------------------------------------------
// Vertical 98-tap box (rows [i-48, i+49], replicate clamp), thread-per-column
// sliding window over a 128-row segment, fused with guided-filter math.
// ---------------------------------------------------------------------------
__global__ __launch_bounds__(256) void k_vbox_ab()
{
    int c  = blockIdx.x * 256 + threadIdx.x;
    int r0 = blockIdx.y * SEG;
    float s1 = 0.0f, s2 = 0.0f;
    for (int k = r0 - PADL; k <= r0 + PADR; ++k) {
        int kc = min(max(k, 0), M - 1);
        s1 += g_t1[kc * NC + c];
        s2 += g_t2[kc * NC + c];
    }
    for (int i = r0; i < r0 + SEG; ++i) {
        float mean  = s1 * BOXNORM;
        float mean2 = s2 * BOXNORM;
        float var = mean2 - mean * mean;
        float A  = var / (var + 1.0f);          // eps = 1
        float bb = mean - A * mean;
        g_t3[i * NC + c] = A;
        g_t4[i * NC + c] = bb;
        int ka = min(i + PADR + 1, M - 1);      // add row i+50
        int kr = max(i - PADL, 0);              // remove row i-48
        s1 += g_t1[ka * NC + c] - g_t1[kr * NC + c];
        s2 += g_t2[ka * NC + c] - g_t2[kr * NC + c];
    }
}

__global__ __launch_bounds__(256) void k_vbox_diff(float* __restrict__ o_diff)
{
    int c  = blockIdx.x * 256 + threadIdx.x;
    int r0 = blockIdx.y * SEG;
    float s1 = 0.0f, s2 = 0.0f;
    for (int k = r0 - PADL; k <= r0 + PADR; ++k) {
        int kc = min(max(k, 0), M - 1);
        s1 += g_t1[kc * NC + c];
        s2 += g_t2[kc * NC + c];
    }
    for (int i = r0; i < r0 + SEG; ++i) {
        float A2  = s1 * BOXNORM;
        float bb2 = s2 * BOXNORM;
        o_diff[i * NC + c] = A2 * g_x[i * NC + c] + bb2;
        int ka = min(i + PADR + 1, M - 1);
        int kr = max(i - PADL, 0);
        s1 += g_t1[ka * NC + c] - g_t1[kr * NC + c];
        s2 += g_t2[ka * NC + c] - g_t2[kr * NC + c];
    }
}

// ---------------------------------------------------------------------------
// Stage 6: diff_adpt = cumsum(clip(rowdiff(diff),0)*sp(ww)); b_adpt -= it.
// ---------------------------------------------------------------------------
__global__ __launch_bounds__(256) void k_dpart(
    const float* __restrict__ diff, const float* __restrict__ ww)
{
    int c   = blockIdx.x * 256 + threadIdx.x;
    int seg = blockIdx.y;
    int i0 = seg * SEG;
    float prev = diff[max(i0 - 1, 0) * NC + c];
    float s = 0.0f;
    for (int i = i0; i < i0 + SEG; ++i) {
        float d = diff[i * NC + c];
        s += fmaxf(d - prev, 0.0f) * softplusf(ww[i * NC + c]);
        prev = d;
    }
    g_pD[seg * NC + c] = s;
}

__global__ __launch_bounds__(256) void k_dscan(
    const float* __restrict__ diff, const float* __restrict__ ww,
    float* __restrict__ o_dadpt, float* __restrict__ o_badpt)
{
    int c   = blockIdx.x * 256 + threadIdx.x;
    int seg = blockIdx.y;
    float cum = 0.0f;
    for (int s = 0; s < seg; ++s) cum += g_pD[s * NC + c];
    int i0 = seg * SEG;
    float prev = diff[max(i0 - 1, 0) * NC + c];
    for (int i = i0; i < i0 + SEG; ++i) {
        int idx = i * NC + c;
        float d = diff[idx];
        cum += fmaxf(d - prev, 0.0f) * softplusf(ww[idx]);
        prev = d;
        o_dadpt[idx] = cum;
        o_badpt[idx] = o_badpt[idx] - cum;   // finalize b_adpt
    }
}

// ---------------------------------------------------------------------------
extern "C" void kernel_launch(void* const* d_in, const int* in_sizes, int n_in,
                              void* d_out, int out_size)
{
    (void)in_sizes; (void)n_in; (void)out_size;
    const float* b     = (const float*)d_in[0];
    const float* bneg  = (const float*)d_in[1];
    const float* fg    = (const float*)d_in[2];
    const float* hX    = (const float*)d_in[3];
    const float* recon = (const float*)d_in[4];
    const float* fmask = (const float*)d_in[5];
    const float* bold  = (const float*)d_in[6];
    // d_in[7] = r (int32 scalar, value 4; hX stride hardcoded)
    const float* w     = (const float*)d_in[8];
    const float* dcol  = (const float*)d_in[9];
    const float* ww    = (const float*)d_in[10];

    float* out     = (float*)d_out;
    float* o_badpt = out;
    float* o_diff  = out + (size_t)PLANE;
    float* o_dadpt = out + 2 * (size_t)PLANE;
    float* o_b     = out + 3 * (size_t)PLANE;

    dim3 gC(NC / 256, NSEGC);   // (16, 6)
    dim3 gF(NC / 256, NSEG);    // (16, 16)

    k_decay_part<<<gC, 256>>>(bneg, dcol);
    k_decay_scan<<<gC, 256>>>(bneg, dcol);
    k_b_part    <<<gF, 256>>>(b, w);
    k_main      <<<gF, 256>>>(b, w, fg, hX, recon, fmask, bold, o_badpt, o_b);
    k_hbox_x    <<<M, 128>>>();
    k_vbox_ab   <<<gF, 256>>>();
    k_hbox_ab   <<<M, 128>>>();
    k_vbox_diff <<<gF, 256>>>(o_diff);
    k_dpart     <<<gF, 256>>>(o_diff, ww);
    k_dscan     <<<gF, 256>>>(o_diff, ww, o_dadpt, o_badpt);
}

// round 7
// speedup vs baseline: 1.9535x; 1.9535x over previous
#include <cuda_runtime.h>

// ---------------------------------------------------------------------------
// stripe_post: column scans + 98-tap guided filter + diff scan.
// M=2048, N=4096, coarse rows MCR=683, hX stride 4.
// Outputs (concatenated): b_adpt, diff, diff_adpt, b  (each M*N f32).
// ---------------------------------------------------------------------------

static constexpr int M     = 2048;
static constexpr int NC    = 4096;
static constexpr int MCR   = 683;
static constexpr int SEG_S = 32;                 // column-scan segment
static constexpr int NSEG_S= 64;
static constexpr int SEG_C = 32;                 // coarse decay segment
static constexpr int NSEG_C= 22;                 // ceil(683/32)
static constexpr int SEG_V = 64;                 // vertical-box segment
static constexpr int NSEG_V= 32;
static constexpr int PADL  = 48;
static constexpr int PADR  = 49;
static constexpr int TAPS  = 98;                 // 2*r taps per axis
static constexpr int SMW   = NC + PADL + PADR;   // 4193
static constexpr float BOXNORM = 1.0f / 9604.0f; // 1/(98*98)
static constexpr float CSC = 683.0f / 2048.0f;   // resize inv_scale

#define PLANE (M * NC)

// Scratch (static device globals: no allocation allowed)
__device__ float g_x [PLANE];
__device__ float g_t1[PLANE];
__device__ float g_t2[PLANE];
__device__ float g_t3[PLANE];   // A plane; reused as inc plane after hbox_ab
__device__ float g_t4[PLANE];   // bb plane
__device__ float g_Dc[MCR * NC];
__device__ float g_pb[NSEG_S * NC];
__device__ float g_pd[NSEG_C * NC];
__device__ float g_pD[NSEG_V * NC];

__device__ __forceinline__ float softplusf(float x) {
    return fmaxf(x, 0.0f) + log1pf(expf(-fabsf(x)));
}

// ---------------------------------------------------------------------------
// Stage 0: decay coarse cumsum (2-pass segmented column scan over 683 rows)
// ---------------------------------------------------------------------------
__global__ __launch_bounds__(256) void k_decay_part(
    const float* __restrict__ bneg, const float* __restrict__ dcol)
{
    int c   = blockIdx.x * 256 + threadIdx.x;
    int seg = blockIdx.y;
    int k0 = seg * SEG_C;
    int k1 = min(MCR, k0 + SEG_C);
    float s = 0.0f;
    for (int k = k0; k < k1; ++k) {
        int idx = k * NC + c;
        s += bneg[idx] * softplusf(dcol[idx]);
    }
    g_pd[seg * NC + c] = s;
}

__global__ __launch_bounds__(256) void k_decay_scan(
    const float* __restrict__ bneg, const float* __restrict__ dcol)
{
    int c   = blockIdx.x * 256 + threadIdx.x;
    int seg = blockIdx.y;
    float run = 0.0f;
    #pragma unroll 8
    for (int s = 0; s < seg; ++s) run += g_pd[s * NC + c];
    int k0 = seg * SEG_C;
    int k1 = min(MCR, k0 + SEG_C);
    for (int k = k0; k < k1; ++k) {
        int idx = k * NC + c;
        run += bneg[idx] * softplusf(dcol[idx]);
        g_Dc[idx] = run;
    }
}

// ---------------------------------------------------------------------------
// Stage 1: b cumsum partials, then fused main scan (branch-free decay lerp):
//   b_full = cumsum(b*sp(w)) + decay_lerp*(1-fg)
//   b_adpt = b_full*fm + b_old*(1-fm);  x = hX[4i] + b_adpt - recon
// ---------------------------------------------------------------------------
__global__ __launch_bounds__(256) void k_b_part(
    const float* __restrict__ b, const float* __restrict__ w)
{
    int c   = blockIdx.x * 256 + threadIdx.x;
    int seg = blockIdx.y;
    int i0 = seg * SEG_S;
    float s = 0.0f;
    #pragma unroll 4
    for (int i = i0; i < i0 + SEG_S; ++i) {
        int idx = i * NC + c;
        s += b[idx] * softplusf(w[idx]);
    }
    g_pb[seg * NC + c] = s;
}

__global__ __launch_bounds__(256) void k_main(
    const float* __restrict__ b,     const float* __restrict__ w,
    const float* __restrict__ fg,    const float* __restrict__ hX,
    const float* __restrict__ recon, const float* __restrict__ fmask,
    const float* __restrict__ bold,
    float* __restrict__ o_badpt, float* __restrict__ o_b)
{
    int c   = blockIdx.x * 256 + threadIdx.x;
    int seg = blockIdx.y;
    float run = 0.0f;
    #pragma unroll 8
    for (int s = 0; s < seg; ++s) run += g_pb[s * NC + c];
    int i0 = seg * SEG_S;

    #pragma unroll 4
    for (int i = i0; i < i0 + SEG_S; ++i) {
        int idx = i * NC + c;
        run += b[idx] * softplusf(w[idx]);

        float sf = fminf(fmaxf((i + 0.5f) * CSC - 0.5f, 0.0f), 682.0f);
        int kk = min((int)sf, 681);
        float f = sf - (float)kk;
        float D0 = g_Dc[kk * NC + c];
        float D1 = g_Dc[(kk + 1) * NC + c];
        float decay = D0 + f * (D1 - D0);

        float bfull = run + decay * (1.0f - fg[idx]);
        float fmv = fmask[idx];
        float badpt = bfull * fmv + bold[idx] * (1.0f - fmv);

        o_b[idx]     = bfull;
        o_badpt[idx] = badpt;   // pre-subtraction; finalized in k_dscan
        g_x[idx]     = hX[(i << 2) * NC + c] + badpt - recon[idx];
    }
}

// ---------------------------------------------------------------------------
// Horizontal 98-tap box (window [j-48, j+49], replicate pad).
// One block per row, 256 threads, chunk of 17 (coprime w/ 32 -> conflict-free
// LDS). One-pass fused sum + sum-of-squares; results staged for coalesced
// global stores.
// ---------------------------------------------------------------------------
__device__ __forceinline__ void hbox_load_row(const float* __restrict__ rp,
                                              float* smin, int tid)
{
    for (int j = tid; j < NC; j += 256) smin[PADL + j] = rp[j];
    if (tid < PADL)             smin[tid]      = rp[0];
    else if (tid < PADL + PADR) smin[NC + tid] = rp[NC - 1];
}

// x -> row-sums of x (g_t1) and x^2 (g_t2), one fused pass
__global__ __launch_bounds__(256) void k_hbox_x()
{
    extern __shared__ float sm[];
    float* smin = sm;              // SMW
    float* so1  = sm + SMW;        // NC
    float* so2  = so1 + NC;        // NC
    int row = blockIdx.x, tid = threadIdx.x;
    hbox_load_row(g_x + row * NC, smin, tid);
    __syncthreads();

    int base = tid * 17;
    if (base < NC) {
        int cnt = min(17, NC - base);
        float s1 = 0.0f, s2 = 0.0f;
        #pragma unroll 14
        for (int u = 0; u < TAPS; ++u) {
            float v = smin[base + u];
            s1 += v; s2 += v * v;
        }
        so1[base] = s1; so2[base] = s2;
        for (int j = 1; j < cnt; ++j) {
            float vn = smin[base + j + TAPS - 1];
            float vo = smin[base + j - 1];
            s1 += vn - vo; s2 += vn * vn - vo * vo;
            so1[base + j] = s1; so2[base + j] = s2;
        }
    }
    __syncthreads();
    for (int j = tid; j < NC; j += 256) {
        g_t1[row * NC + j] = so1[j];
        g_t2[row * NC + j] = so2[j];
    }
}

// A (g_t3) -> g_t1 ; bb (g_t4) -> g_t2   (two single-sum passes)
__global__ __launch_bounds__(256) void k_hbox_ab()
{
    __shared__ float smin[SMW];
    __shared__ float so[NC];
    int row = blockIdx.x, tid = threadIdx.x;
    int base = tid * 17;
    int cnt  = (base < NC) ? min(17, NC - base) : 0;

    hbox_load_row(g_t3 + row * NC, smin, tid);
    __syncthreads();
    if (cnt) {
        float s = 0.0f;
        #pragma unroll 14
        for (int u = 0; u < TAPS; ++u) s += smin[base + u];
        so[base] = s;
        for (int j = 1; j < cnt; ++j) {
            s += smin[base + j + TAPS - 1] - smin[base + j - 1];
            so[base + j] = s;
        }
    }
    __syncthreads();
    for (int j = tid; j < NC; j += 256) g_t1[row * NC + j] = so[j];
    hbox_load_row(g_t4 + row * NC, smin, tid);   // disjoint from so: no hazard
    __syncthreads();
    if (cnt) {
        float s = 0.0f;
        #pragma unroll 14
        for (int u = 0; u < TAPS; ++u) s += smin[base + u];
        so[base] = s;
        for (int j = 1; j < cnt; ++j) {
            s += smin[base + j + TAPS - 1] - smin[base + j - 1];
            so[base + j] = s;
        }
    }
    __syncthreads();
    for (int j = tid; j < NC; j += 256) g_t2[row * NC + j] = so[j];
}

// ---------------------------------------------------------------------------
// Vertical 98-tap box (rows [i-48, i+49], replicate clamp), thread-per-column
// sliding window, SEG_V=64, clamp only on boundary segments.
// ---------------------------------------------------------------------------
template <bool CLAMP>
__device__ __forceinline__ void vbox_ab_body(int c, int r0)
{
    float s1 = 0.0f, s2 = 0.0f;
    #pragma unroll 2
    for (int k = r0 - PADL; k <= r0 + PADR; ++k) {
        int kc = CLAMP ? min(max(k, 0), M - 1) : k;
        s1 += g_t1[kc * NC + c];
        s2 += g_t2[kc * NC + c];
    }
    #pragma unroll 4
    for (int i = r0; i < r0 + SEG_V; ++i) {
        float mean  = s1 * BOXNORM;
        float mean2 = s2 * BOXNORM;
        float var = mean2 - mean * mean;
        float A  = var / (var + 1.0f);          // eps = 1
        g_t3[i * NC + c] = A;
        g_t4[i * NC + c] = mean - A * mean;
        int ka = CLAMP ? min(i + PADR + 1, M - 1) : i + PADR + 1;
        int kr = CLAMP ? max(i - PADL, 0)         : i - PADL;
        s1 += g_t1[ka * NC + c] - g_t1[kr * NC + c];
        s2 += g_t2[ka * NC + c] - g_t2[kr * NC + c];
    }
}

__global__ __launch_bounds__(256) void k_vbox_ab()
{
    int c  = blockIdx.x * 256 + threadIdx.x;
    int r0 = blockIdx.y * SEG_V;
    if (blockIdx.y == 0 || blockIdx.y == NSEG_V - 1) vbox_ab_body<true >(c, r0);
    else                                             vbox_ab_body<false>(c, r0);
}

// Final vbox + diff + fused diff-scan prep:
//   diff = A2*x + bb2 ; inc = max(diff[i]-diff[i-1],0)*sp(ww) -> g_t3
//   per-segment partial of inc -> g_pD
template <bool CLAMP>
__device__ __forceinline__ void vbox_diff_body(
    int c, int r0, const float* __restrict__ ww, float* __restrict__ o_diff)
{
    int ibeg = CLAMP ? max(r0 - 1, 0) : r0 - 1;
    float s1 = 0.0f, s2 = 0.0f;
    #pragma unroll 2
    for (int k = ibeg - PADL; k <= ibeg + PADR; ++k) {
        int kc = CLAMP ? min(max(k, 0), M - 1) : k;
        s1 += g_t1[kc * NC + c];
        s2 += g_t2[kc * NC + c];
    }
    float prev = 0.0f, acc = 0.0f;
    #pragma unroll 4
    for (int i = ibeg; i < r0 + SEG_V; ++i) {
        int idx = i * NC + c;
        float dv = fmaf(s1 * BOXNORM, g_x[idx], s2 * BOXNORM);
        if (i < r0) {
            prev = dv;                            // warm-up row (r0-1)
        } else {
            if (CLAMP && i == 0) prev = dv;       // prepend: inc[0] = 0
            float ic = fmaxf(dv - prev, 0.0f) * softplusf(ww[idx]);
            o_diff[idx] = dv;
            g_t3[idx]   = ic;                     // inc plane (t3 reused)
            acc += ic;
            prev = dv;
        }
        int ka = CLAMP ? min(i + PADR + 1, M - 1) : i + PADR + 1;
        int kr = CLAMP ? max(i - PADL, 0)         : i - PADL;
        s1 += g_t1[ka * NC + c] - g_t1[kr * NC + c];
        s2 += g_t2[ka * NC + c] - g_t2[kr * NC + c];
    }
    g_pD[blockIdx.y * NC + c] = acc;
}

__global__ __launch_bounds__(256) void k_vbox_diff(
    const float* __restrict__ ww, float* __restrict__ o_diff)
{
    int c  = blockIdx.x * 256 + threadIdx.x;
    int r0 = blockIdx.y * SEG_V;
    if (blockIdx.y == 0 || blockIdx.y == NSEG_V - 1) vbox_diff_body<true >(c, r0, ww, o_diff);
    else                                             vbox_diff_body<false>(c, r0, ww, o_diff);
}

// ---------------------------------------------------------------------------
// Stage 6: diff_adpt = cumsum(inc); b_adpt -= diff_adpt
// ---------------------------------------------------------------------------
__global__ __launch_bounds__(256) void k_dscan(
    float* __restrict__ o_dadpt, float* __restrict__ o_badpt)
{
    int c   = blockIdx.x * 256 + threadIdx.x;
    int seg = blockIdx.y;
    float cum = 0.0f;
    #pragma unroll 8
    for (int s = 0; s < seg; ++s) cum += g_pD[s * NC + c];
    int i0 = seg * SEG_V;
    #pragma unroll 4
    for (int i = i0; i < i0 + SEG_V; ++i) {
        int idx = i * NC + c;
        cum += g_t3[idx];
        o_dadpt[idx] = cum;
        o_badpt[idx] = o_badpt[idx] - cum;   // finalize b_adpt
    }
}

// ---------------------------------------------------------------------------
extern "C" void kernel_launch(void* const* d_in, const int* in_sizes, int n_in,
                              void* d_out, int out_size)
{
    (void)in_sizes; (void)n_in; (void)out_size;
    const float* b     = (const float*)d_in[0];
    const float* bneg  = (const float*)d_in[1];
    const float* fg    = (const float*)d_in[2];
    const float* hX    = (const float*)d_in[3];
    const float* recon = (const float*)d_in[4];
    const float* fmask = (const float*)d_in[5];
    const float* bold  = (const float*)d_in[6];
    // d_in[7] = r (int32 scalar, value 4; hX stride hardcoded)
    const float* w     = (const float*)d_in[8];
    const float* dcol  = (const float*)d_in[9];
    const float* ww    = (const float*)d_in[10];

    float* out     = (float*)d_out;
    float* o_badpt = out;
    float* o_diff  = out + (size_t)PLANE;
    float* o_dadpt = out + 2 * (size_t)PLANE;
    float* o_b     = out + 3 * (size_t)PLANE;

    // k_hbox_x needs 49.5KB smem (> 48KB static limit) -> dynamic + opt-in
    int hx_smem = (SMW + 2 * NC) * (int)sizeof(float);
    cudaFuncSetAttribute(k_hbox_x, cudaFuncAttributeMaxDynamicSharedMemorySize,
                         hx_smem);

    dim3 gC(NC / 256, NSEG_C);   // (16, 22)
    dim3 gS(NC / 256, NSEG_S);   // (16, 64)
    dim3 gV(NC / 256, NSEG_V);   // (16, 32)

    k_decay_part<<<gC, 256>>>(bneg, dcol);
    k_decay_scan<<<gC, 256>>>(bneg, dcol);
    k_b_part    <<<gS, 256>>>(b, w);
    k_main      <<<gS, 256>>>(b, w, fg, hX, recon, fmask, bold, o_badpt, o_b);
    k_hbox_x    <<<M, 256, hx_smem>>>();
    k_vbox_ab   <<<gV, 256>>>();
    k_hbox_ab   <<<M, 256>>>();
    k_vbox_diff <<<gV, 256>>>(ww, o_diff);
    k_dscan     <<<gV, 256>>>(o_dadpt, o_badpt);
}

// round 8
// speedup vs baseline: 2.5285x; 1.2944x over previous
#include <cuda_runtime.h>

// ---------------------------------------------------------------------------
// stripe_post: column scans + 98-tap guided filter + diff scan.
// M=2048, N=4096, coarse rows MCR=683, hX stride 4.
// Outputs (concatenated): b_adpt, diff, diff_adpt, b  (each M*N f32).
//
// Structure (8 kernels, all float4-vectorized on the column axis):
//   decay_part/scan : coarse column cumsum (683 rows)
//   b_part / main   : fine column cumsum + fusion -> b, b_adpt, x
//   vbox_x          : vertical 98-tap sums of x and x^2      (box1 part 1)
//   hAB   (row krn) : hbox of those -> A,bb -> hbox of A,bb  (box1 p2 + box2 p1)
//   vbox_diff       : vertical 98-tap of hA,hbb -> diff, inc (box2 part 2)
//   dscan           : column cumsum of inc -> diff_adpt, finalize b_adpt
// ---------------------------------------------------------------------------

static constexpr int M      = 2048;
static constexpr int NC     = 4096;
static constexpr int NC4    = 1024;              // NC/4
static constexpr int MCR    = 683;
static constexpr int SEG_S  = 32;                // fine column-scan segment
static constexpr int NSEG_S = 64;
static constexpr int SEG_C  = 32;                // coarse decay segment
static constexpr int NSEG_C = 22;                // ceil(683/32)
static constexpr int SEG_V  = 32;                // vertical-box segment
static constexpr int NSEG_V = 64;
static constexpr int PADL   = 48;
static constexpr int PADR   = 49;
static constexpr int TAPS   = 98;                // 2*r taps per axis
static constexpr int SMW    = NC + PADL + PADR;  // 4193
static constexpr float BOXNORM = 1.0f / 9604.0f; // 1/(98*98)
static constexpr float CSC = 683.0f / 2048.0f;   // resize inv_scale

#define PLANE (M * NC)

// Scratch (static device globals: no allocation allowed)
__device__ float g_x [PLANE];
__device__ float g_t1[PLANE];   // vbox(x) sums; later reused as inc plane
__device__ float g_t2[PLANE];   // vbox(x^2) sums
__device__ float g_t3[PLANE];   // hbox(A)
__device__ float g_t4[PLANE];   // hbox(bb)
__device__ float g_Dc[MCR * NC];
__device__ float g_pb[NSEG_S * NC];
__device__ float g_pd[NSEG_C * NC];
__device__ float g_pD[NSEG_V * NC];

// ---- float4 helpers -------------------------------------------------------
__device__ __forceinline__ float4 ld4(const float* p, int i4) {
    return reinterpret_cast<const float4*>(p)[i4];
}
__device__ __forceinline__ void st4(float* p, int i4, float4 v) {
    reinterpret_cast<float4*>(p)[i4] = v;
}
__device__ __forceinline__ float4 operator+(float4 a, float4 b) {
    return make_float4(a.x+b.x, a.y+b.y, a.z+b.z, a.w+b.w);
}
__device__ __forceinline__ float4 operator-(float4 a, float4 b) {
    return make_float4(a.x-b.x, a.y-b.y, a.z-b.z, a.w-b.w);
}
__device__ __forceinline__ float4 operator*(float4 a, float4 b) {
    return make_float4(a.x*b.x, a.y*b.y, a.z*b.z, a.w*b.w);
}
__device__ __forceinline__ float4 operator*(float s, float4 b) {
    return make_float4(s*b.x, s*b.y, s*b.z, s*b.w);
}
__device__ __forceinline__ float4 operator-(float s, float4 b) {
    return make_float4(s-b.x, s-b.y, s-b.z, s-b.w);
}
__device__ __forceinline__ float4 f4zero() { return make_float4(0.f,0.f,0.f,0.f); }
__device__ __forceinline__ float4 max4(float4 a, float s) {
    return make_float4(fmaxf(a.x,s), fmaxf(a.y,s), fmaxf(a.z,s), fmaxf(a.w,s));
}

__device__ __forceinline__ float softplusf(float x) {
    // tolerance is 1e-3; fast intrinsics are ~1e-7 absolute here
    return fmaxf(x, 0.0f) + __logf(1.0f + __expf(-fabsf(x)));
}
__device__ __forceinline__ float4 sp4(float4 v) {
    return make_float4(softplusf(v.x), softplusf(v.y),
                       softplusf(v.z), softplusf(v.w));
}

// ---------------------------------------------------------------------------
// Stage 0: decay coarse cumsum (2-pass segmented column scan over 683 rows)
// ---------------------------------------------------------------------------
__global__ __launch_bounds__(256) void k_decay_part(
    const float* __restrict__ bneg, const float* __restrict__ dcol)
{
    int c4  = blockIdx.x * 256 + threadIdx.x;
    int seg = blockIdx.y;
    int k0 = seg * SEG_C;
    int k1 = min(MCR, k0 + SEG_C);
    float4 s = f4zero();
    #pragma unroll 4
    for (int k = k0; k < k1; ++k) {
        int i4 = k * NC4 + c4;
        s = s + ld4(bneg, i4) * sp4(ld4(dcol, i4));
    }
    st4(g_pd, seg * NC4 + c4, s);
}

__global__ __launch_bounds__(256) void k_decay_scan(
    const float* __restrict__ bneg, const float* __restrict__ dcol)
{
    int c4  = blockIdx.x * 256 + threadIdx.x;
    int seg = blockIdx.y;
    float4 run = f4zero();
    #pragma unroll 4
    for (int s = 0; s < seg; ++s) run = run + ld4(g_pd, s * NC4 + c4);
    int k0 = seg * SEG_C;
    int k1 = min(MCR, k0 + SEG_C);
    for (int k = k0; k < k1; ++k) {
        int i4 = k * NC4 + c4;
        run = run + ld4(bneg, i4) * sp4(ld4(dcol, i4));
        st4(g_Dc, i4, run);
    }
}

// ---------------------------------------------------------------------------
// Stage 1: b cumsum partials, then fused main scan:
//   b_full = cumsum(b*sp(w)) + decay_lerp*(1-fg)
//   b_adpt = b_full*fm + b_old*(1-fm);  x = hX[4i] + b_adpt - recon
// ---------------------------------------------------------------------------
__global__ __launch_bounds__(256) void k_b_part(
    const float* __restrict__ b, const float* __restrict__ w)
{
    int c4  = blockIdx.x * 256 + threadIdx.x;
    int seg = blockIdx.y;
    int i0 = seg * SEG_S;
    float4 s = f4zero();
    #pragma unroll 4
    for (int i = i0; i < i0 + SEG_S; ++i) {
        int i4 = i * NC4 + c4;
        s = s + ld4(b, i4) * sp4(ld4(w, i4));
    }
    st4(g_pb, seg * NC4 + c4, s);
}

__global__ __launch_bounds__(256) void k_main(
    const float* __restrict__ b,     const float* __restrict__ w,
    const float* __restrict__ fg,    const float* __restrict__ hX,
    const float* __restrict__ recon, const float* __restrict__ fmask,
    const float* __restrict__ bold,
    float* __restrict__ o_badpt, float* __restrict__ o_b)
{
    int c4  = blockIdx.x * 256 + threadIdx.x;
    int seg = blockIdx.y;
    float4 run = f4zero();
    #pragma unroll 4
    for (int s = 0; s < seg; ++s) run = run + ld4(g_pb, s * NC4 + c4);
    int i0 = seg * SEG_S;

    #pragma unroll 2
    for (int i = i0; i < i0 + SEG_S; ++i) {
        int i4 = i * NC4 + c4;
        run = run + ld4(b, i4) * sp4(ld4(w, i4));

        float sf = fminf(fmaxf((i + 0.5f) * CSC - 0.5f, 0.0f), 682.0f);
        int kk = min((int)sf, 681);
        float f = sf - (float)kk;
        float4 D0 = ld4(g_Dc, kk * NC4 + c4);
        float4 D1 = ld4(g_Dc, (kk + 1) * NC4 + c4);
        float4 decay = D0 + f * (D1 - D0);

        float4 bfull = run + decay * (1.0f - ld4(fg, i4));
        float4 fmv = ld4(fmask, i4);
        float4 badpt = bfull * fmv + ld4(bold, i4) * (1.0f - fmv);

        st4(o_b, i4, bfull);
        st4(o_badpt, i4, badpt);   // pre-subtraction; finalized in k_dscan
        st4(g_x, i4, ld4(hX, (i << 2) * NC4 + c4) + badpt - ld4(recon, i4));
    }
}

// ---------------------------------------------------------------------------
// Vertical 98-tap sums of x and x^2 (rows [i-48, i+49], replicate clamp).
// Thread-per-4-columns sliding window over SEG_V rows. box1 part 1.
// ---------------------------------------------------------------------------
template <bool CLAMP>
__device__ __forceinline__ void vbox_x_body(int c4, int r0)
{
    float4 s1 = f4zero(), s2 = f4zero();
    #pragma unroll 2
    for (int k = r0 - PADL; k <= r0 + PADR; ++k) {
        int kc = CLAMP ? min(max(k, 0), M - 1) : k;
        float4 v = ld4(g_x, kc * NC4 + c4);
        s1 = s1 + v; s2 = s2 + v * v;
    }
    #pragma unroll 4
    for (int i = r0; i < r0 + SEG_V; ++i) {
        st4(g_t1, i * NC4 + c4, s1);
        st4(g_t2, i * NC4 + c4, s2);
        int ka = CLAMP ? min(i + PADR + 1, M - 1) : i + PADR + 1;
        int kr = CLAMP ? max(i - PADL, 0)         : i - PADL;
        float4 va = ld4(g_x, ka * NC4 + c4);
        float4 vr = ld4(g_x, kr * NC4 + c4);
        s1 = s1 + va - vr;
        s2 = s2 + va * va - vr * vr;
    }
}

__global__ __launch_bounds__(256) void k_vbox_x()
{
    int c4 = blockIdx.x * 256 + threadIdx.x;
    int r0 = blockIdx.y * SEG_V;
    if (blockIdx.y < 2 || blockIdx.y >= NSEG_V - 2) vbox_x_body<true >(c4, r0);
    else                                            vbox_x_body<false>(c4, r0);
}

// ---------------------------------------------------------------------------
// Row kernel: hbox of (v1,v2) -> mean,mean2 -> A,bb pointwise -> hbox of A,bb.
// One block per row, 256 threads, chunk 17 (coprime with 32 -> conflict-free
// LDS). All window work in smem; outputs staged for coalesced stores.
// ---------------------------------------------------------------------------
__global__ __launch_bounds__(256) void k_hAB()
{
    extern __shared__ float sm[];
    float* sv1 = sm;                 // SMW  (vbox sums of x;   staging out A2)
    float* sv2 = sv1 + SMW;          // SMW  (vbox sums of x^2; staging out bb2)
    float* sA  = sv2 + SMW;          // SMW
    float* sB  = sA + SMW;           // SMW
    int row = blockIdx.x, tid = threadIdx.x;

    const float* r1 = g_t1 + row * NC;
    const float* r2 = g_t2 + row * NC;
    for (int j = tid; j < NC; j += 256) { sv1[PADL + j] = r1[j]; sv2[PADL + j] = r2[j]; }
    if (tid < PADL)             { sv1[tid] = r1[0];           sv2[tid] = r2[0]; }
    else if (tid < PADL + PADR) { sv1[NC + tid] = r1[NC - 1]; sv2[NC + tid] = r2[NC - 1]; }
    __syncthreads();

    int base = tid * 17;
    int cnt  = (base < NC) ? min(17, NC - base) : 0;

    // pass 1: window sums of v1,v2 -> A,bb per column
    if (cnt) {
        float s1 = 0.0f, s2 = 0.0f;
        #pragma unroll 14
        for (int u = 0; u < TAPS; ++u) { s1 += sv1[base + u]; s2 += sv2[base + u]; }
        for (int j = 0; ; ) {
            float mean  = s1 * BOXNORM;
            float mean2 = s2 * BOXNORM;
            float var = mean2 - mean * mean;
            float A = var / (var + 1.0f);       // eps = 1
            sA[PADL + base + j] = A;
            sB[PADL + base + j] = mean - A * mean;
            if (++j >= cnt) break;
            s1 += sv1[base + j + TAPS - 1] - sv1[base + j - 1];
            s2 += sv2[base + j + TAPS - 1] - sv2[base + j - 1];
        }
    }
    __syncthreads();
    if (tid < PADL)             { sA[tid] = sA[PADL];               sB[tid] = sB[PADL]; }
    else if (tid < PADL + PADR) { sA[NC + tid] = sA[PADL + NC - 1]; sB[NC + tid] = sB[PADL + NC - 1]; }
    __syncthreads();

    // pass 2: window sums of A,bb -> staged in sv1,sv2 (dead after pass 1)
    if (cnt) {
        float sa = 0.0f, sb = 0.0f;
        #pragma unroll 14
        for (int u = 0; u < TAPS; ++u) { sa += sA[base + u]; sb += sB[base + u]; }
        sv1[base] = sa; sv2[base] = sb;
        for (int j = 1; j < cnt; ++j) {
            sa += sA[base + j + TAPS - 1] - sA[base + j - 1];
            sb += sB[base + j + TAPS - 1] - sB[base + j - 1];
            sv1[base + j] = sa; sv2[base + j] = sb;
        }
    }
    __syncthreads();
    for (int j = tid; j < NC; j += 256) {
        g_t3[row * NC + j] = sv1[j];
        g_t4[row * NC + j] = sv2[j];
    }
}

// ---------------------------------------------------------------------------
// Final vertical 98-tap of hA,hbb + diff + fused diff-scan prep:
//   diff = A2*x + bb2 ; inc = max(diff[i]-diff[i-1],0)*sp(ww) -> g_t1
//   per-segment partial of inc -> g_pD
// ---------------------------------------------------------------------------
template <bool CLAMP>
__device__ __forceinline__ void vbox_diff_body(
    int c4, int r0, int seg, const float* __restrict__ ww,
    float* __restrict__ o_diff)
{
    int ibeg = CLAMP ? max(r0 - 1, 0) : r0 - 1;
    float4 s1 = f4zero(), s2 = f4zero();
    #pragma unroll 2
    for (int k = ibeg - PADL; k <= ibeg + PADR; ++k) {
        int kc = CLAMP ? min(max(k, 0), M - 1) : k;
        s1 = s1 + ld4(g_t3, kc * NC4 + c4);
        s2 = s2 + ld4(g_t4, kc * NC4 + c4);
    }
    float4 prev = f4zero(), acc = f4zero();
    #pragma unroll 2
    for (int i = ibeg; i < r0 + SEG_V; ++i) {
        int i4 = i * NC4 + c4;
        float4 dv = (BOXNORM * s1) * ld4(g_x, i4) + BOXNORM * s2;
        if (i < r0) {
            prev = dv;                           // warm-up row (r0-1)
        } else {
            if (CLAMP && i == 0) prev = dv;      // prepend: inc[0] = 0
            float4 ic = max4(dv - prev, 0.0f) * sp4(ld4(ww, i4));
            st4(o_diff, i4, dv);
            st4(g_t1, i4, ic);                   // inc plane (t1 reused)
            acc = acc + ic;
            prev = dv;
        }
        int ka = CLAMP ? min(i + PADR + 1, M - 1) : i + PADR + 1;
        int kr = CLAMP ? max(i - PADL, 0)         : i - PADL;
        s1 = s1 + ld4(g_t3, ka * NC4 + c4) - ld4(g_t3, kr * NC4 + c4);
        s2 = s2 + ld4(g_t4, ka * NC4 + c4) - ld4(g_t4, kr * NC4 + c4);
    }
    st4(g_pD, seg * NC4 + c4, acc);
}

__global__ __launch_bounds__(256) void k_vbox_diff(
    const float* __restrict__ ww, float* __restrict__ o_diff)
{
    int c4 = blockIdx.x * 256 + threadIdx.x;
    int seg = blockIdx.y;
    int r0 = seg * SEG_V;
    if (seg < 2 || seg >= NSEG_V - 2) vbox_diff_body<true >(c4, r0, seg, ww, o_diff);
    else                              vbox_diff_body<false>(c4, r0, seg, ww, o_diff);
}

// ---------------------------------------------------------------------------
// Stage 6: diff_adpt = cumsum(inc); b_adpt -= diff_adpt
// ---------------------------------------------------------------------------
__global__ __launch_bounds__(256) void k_dscan(
    float* __restrict__ o_dadpt, float* __restrict__ o_badpt)
{
    int c4  = blockIdx.x * 256 + threadIdx.x;
    int seg = blockIdx.y;
    float4 cum = f4zero();
    #pragma unroll 4
    for (int s = 0; s < seg; ++s) cum = cum + ld4(g_pD, s * NC4 + c4);
    int i0 = seg * SEG_V;
    #pragma unroll 4
    for (int i = i0; i < i0 + SEG_V; ++i) {
        int i4 = i * NC4 + c4;
        cum = cum + ld4(g_t1, i4);
        st4(o_dadpt, i4, cum);
        st4(o_badpt, i4, ld4(o_badpt, i4) - cum);   // finalize b_adpt
    }
}

// ---------------------------------------------------------------------------
extern "C" void kernel_launch(void* const* d_in, const int* in_sizes, int n_in,
                              void* d_out, int out_size)
{
    (void)in_sizes; (void)n_in; (void)out_size;
    const float* b     = (const float*)d_in[0];
    const float* bneg  = (const float*)d_in[1];
    const float* fg    = (const float*)d_in[2];
    const float* hX    = (const float*)d_in[3];
    const float* recon = (const float*)d_in[4];
    const float* fmask = (const float*)d_in[5];
    const float* bold  = (const float*)d_in[6];
    // d_in[7] = r (int32 scalar, value 4; hX stride hardcoded)
    const float* w     = (const float*)d_in[8];
    const float* dcol  = (const float*)d_in[9];
    const float* ww    = (const float*)d_in[10];

    float* out     = (float*)d_out;
    float* o_badpt = out;
    float* o_diff  = out + (size_t)PLANE;
    float* o_dadpt = out + 2 * (size_t)PLANE;
    float* o_b     = out + 3 * (size_t)PLANE;

    // k_hAB needs 4*SMW*4 = 67088 B smem -> dynamic + opt-in
    int hab_smem = 4 * SMW * (int)sizeof(float);
    cudaFuncSetAttribute(k_hAB, cudaFuncAttributeMaxDynamicSharedMemorySize,
                         hab_smem);

    dim3 gC(NC4 / 256, NSEG_C);   // (4, 22)
    dim3 gS(NC4 / 256, NSEG_S);   // (4, 64)
    dim3 gV(NC4 / 256, NSEG_V);   // (4, 64)

    k_decay_part<<<gC, 256>>>(bneg, dcol);
    k_decay_scan<<<gC, 256>>>(bneg, dcol);
    k_b_part    <<<gS, 256>>>(b, w);
    k_main      <<<gS, 256>>>(b, w, fg, hX, recon, fmask, bold, o_badpt, o_b);
    k_vbox_x    <<<gV, 256>>>();
    k_hAB       <<<M, 256, hab_smem>>>();
    k_vbox_diff <<<gV, 256>>>(ww, o_diff);
    k_dscan     <<<gV, 256>>>(o_dadpt, o_badpt);
}

// round 9
// speedup vs baseline: 2.9079x; 1.1501x over previous
#include <cuda_runtime.h>

// ---------------------------------------------------------------------------
// stripe_post: column scans + 98-tap guided filter + diff scan.
// M=2048, N=4096, coarse rows MCR=683, hX stride 4.
// Outputs (concatenated): b_adpt, diff, diff_adpt, b  (each M*N f32).
//
// Structure (8 kernels, float4-vectorized, occupancy-tuned):
//   decay_part/scan : coarse column cumsum (683 rows)
//   b_part / main   : fine column cumsum + fusion -> b, b_adpt, x
//   vbox_x          : vertical 98-tap sums of x and x^2      (box1 part 1)
//   hAB   (row krn) : hbox of those -> A,bb -> hbox of A,bb  (box1 p2 + box2 p1)
//   vbox_diff       : vertical 98-tap of hA,hbb -> diff, inc (box2 part 2)
//   dscan           : column cumsum of inc -> diff_adpt, finalize b_adpt
// ---------------------------------------------------------------------------

static constexpr int M      = 2048;
static constexpr int NC     = 4096;
static constexpr int NC4    = 1024;              // NC/4
static constexpr int MCR    = 683;
static constexpr int SEG_S  = 16;                // fine column-scan segment
static constexpr int NSEG_S = 128;
static constexpr int SEG_C  = 32;                // coarse decay segment
static constexpr int NSEG_C = 22;                // ceil(683/32)
static constexpr int SEG_V  = 16;                // vertical-box segment
static constexpr int NSEG_V = 128;
static constexpr int PADL   = 48;
static constexpr int PADR   = 49;
static constexpr int TAPS   = 98;                // 2*r taps per axis
static constexpr int SMW    = NC + PADL + PADR;  // 4193
static constexpr int HCH    = 9;                 // hAB per-thread chunk (coprime 32)
static constexpr float BOXNORM = 1.0f / 9604.0f; // 1/(98*98)
static constexpr float CSC = 683.0f / 2048.0f;   // resize inv_scale

#define PLANE (M * NC)

// Scratch (static device globals: no allocation allowed)
__device__ float g_x [PLANE];
__device__ float g_t1[PLANE];   // vbox(x) sums; later reused as inc plane
__device__ float g_t2[PLANE];   // vbox(x^2) sums
__device__ float g_t3[PLANE];   // hbox(A)
__device__ float g_t4[PLANE];   // hbox(bb)
__device__ float g_Dc[MCR * NC];
__device__ float g_pb[NSEG_S * NC];
__device__ float g_pd[NSEG_C * NC];
__device__ float g_pD[NSEG_V * NC];

// ---- float4 helpers -------------------------------------------------------
__device__ __forceinline__ float4 ld4(const float* p, int i4) {
    return reinterpret_cast<const float4*>(p)[i4];
}
__device__ __forceinline__ void st4(float* p, int i4, float4 v) {
    reinterpret_cast<float4*>(p)[i4] = v;
}
__device__ __forceinline__ float4 operator+(float4 a, float4 b) {
    return make_float4(a.x+b.x, a.y+b.y, a.z+b.z, a.w+b.w);
}
__device__ __forceinline__ float4 operator-(float4 a, float4 b) {
    return make_float4(a.x-b.x, a.y-b.y, a.z-b.z, a.w-b.w);
}
__device__ __forceinline__ float4 operator*(float4 a, float4 b) {
    return make_float4(a.x*b.x, a.y*b.y, a.z*b.z, a.w*b.w);
}
__device__ __forceinline__ float4 operator*(float s, float4 b) {
    return make_float4(s*b.x, s*b.y, s*b.z, s*b.w);
}
__device__ __forceinline__ float4 operator-(float s, float4 b) {
    return make_float4(s-b.x, s-b.y, s-b.z, s-b.w);
}
__device__ __forceinline__ float4 f4zero() { return make_float4(0.f,0.f,0.f,0.f); }
__device__ __forceinline__ float4 max4(float4 a, float s) {
    return make_float4(fmaxf(a.x,s), fmaxf(a.y,s), fmaxf(a.z,s), fmaxf(a.w,s));
}

__device__ __forceinline__ float softplusf(float x) {
    // tolerance is 1e-3; fast intrinsics are ~1e-7 absolute here
    return fmaxf(x, 0.0f) + __logf(1.0f + __expf(-fabsf(x)));
}
__device__ __forceinline__ float4 sp4(float4 v) {
    return make_float4(softplusf(v.x), softplusf(v.y),
                       softplusf(v.z), softplusf(v.w));
}

// ---------------------------------------------------------------------------
// Stage 0: decay coarse cumsum (2-pass segmented column scan over 683 rows)
// ---------------------------------------------------------------------------
__global__ __launch_bounds__(256) void k_decay_part(
    const float* __restrict__ bneg, const float* __restrict__ dcol)
{
    int c4  = blockIdx.x * 256 + threadIdx.x;
    int seg = blockIdx.y;
    int k0 = seg * SEG_C;
    int k1 = min(MCR, k0 + SEG_C);
    float4 s = f4zero();
    #pragma unroll 4
    for (int k = k0; k < k1; ++k) {
        int i4 = k * NC4 + c4;
        s = s + ld4(bneg, i4) * sp4(ld4(dcol, i4));
    }
    st4(g_pd, seg * NC4 + c4, s);
}

__global__ __launch_bounds__(256) void k_decay_scan(
    const float* __restrict__ bneg, const float* __restrict__ dcol)
{
    int c4  = blockIdx.x * 256 + threadIdx.x;
    int seg = blockIdx.y;
    float4 run = f4zero();
    #pragma unroll 4
    for (int s = 0; s < seg; ++s) run = run + ld4(g_pd, s * NC4 + c4);
    int k0 = seg * SEG_C;
    int k1 = min(MCR, k0 + SEG_C);
    for (int k = k0; k < k1; ++k) {
        int i4 = k * NC4 + c4;
        run = run + ld4(bneg, i4) * sp4(ld4(dcol, i4));
        st4(g_Dc, i4, run);
    }
}

// ---------------------------------------------------------------------------
// Stage 1: b cumsum partials, then fused main scan:
//   b_full = cumsum(b*sp(w)) + decay_lerp*(1-fg)
//   b_adpt = b_full*fm + b_old*(1-fm);  x = hX[4i] + b_adpt - recon
// ---------------------------------------------------------------------------
__global__ __launch_bounds__(256) void k_b_part(
    const float* __restrict__ b, const float* __restrict__ w)
{
    int c4  = blockIdx.x * 256 + threadIdx.x;
    int seg = blockIdx.y;
    int i0 = seg * SEG_S;
    float4 s = f4zero();
    #pragma unroll 4
    for (int i = i0; i < i0 + SEG_S; ++i) {
        int i4 = i * NC4 + c4;
        s = s + ld4(b, i4) * sp4(ld4(w, i4));
    }
    st4(g_pb, seg * NC4 + c4, s);
}

__global__ __launch_bounds__(256) void k_main(
    const float* __restrict__ b,     const float* __restrict__ w,
    const float* __restrict__ fg,    const float* __restrict__ hX,
    const float* __restrict__ recon, const float* __restrict__ fmask,
    const float* __restrict__ bold,
    float* __restrict__ o_badpt, float* __restrict__ o_b)
{
    int c4  = blockIdx.x * 256 + threadIdx.x;
    int seg = blockIdx.y;
    float4 run = f4zero();
    #pragma unroll 8
    for (int s = 0; s < seg; ++s) run = run + ld4(g_pb, s * NC4 + c4);
    int i0 = seg * SEG_S;

    #pragma unroll 2
    for (int i = i0; i < i0 + SEG_S; ++i) {
        int i4 = i * NC4 + c4;
        run = run + ld4(b, i4) * sp4(ld4(w, i4));

        float sf = fminf(fmaxf((i + 0.5f) * CSC - 0.5f, 0.0f), 682.0f);
        int kk = min((int)sf, 681);
        float f = sf - (float)kk;
        float4 D0 = ld4(g_Dc, kk * NC4 + c4);
        float4 D1 = ld4(g_Dc, (kk + 1) * NC4 + c4);
        float4 decay = D0 + f * (D1 - D0);

        float4 bfull = run + decay * (1.0f - ld4(fg, i4));
        float4 fmv = ld4(fmask, i4);
        float4 badpt = bfull * fmv + ld4(bold, i4) * (1.0f - fmv);

        st4(o_b, i4, bfull);
        st4(o_badpt, i4, badpt);   // pre-subtraction; finalized in k_dscan
        st4(g_x, i4, ld4(hX, (i << 2) * NC4 + c4) + badpt - ld4(recon, i4));
    }
}

// ---------------------------------------------------------------------------
// Vertical 98-tap sums of x and x^2 (rows [i-48, i+49], replicate clamp).
// Thread-per-4-columns sliding window over SEG_V rows. box1 part 1.
// ---------------------------------------------------------------------------
template <bool CLAMP>
__device__ __forceinline__ void vbox_x_body(int c4, int r0)
{
    float4 s1 = f4zero(), s2 = f4zero();
    #pragma unroll 2
    for (int k = r0 - PADL; k <= r0 + PADR; ++k) {
        int kc = CLAMP ? min(max(k, 0), M - 1) : k;
        float4 v = ld4(g_x, kc * NC4 + c4);
        s1 = s1 + v; s2 = s2 + v * v;
    }
    #pragma unroll 4
    for (int i = r0; i < r0 + SEG_V; ++i) {
        st4(g_t1, i * NC4 + c4, s1);
        st4(g_t2, i * NC4 + c4, s2);
        int ka = CLAMP ? min(i + PADR + 1, M - 1) : i + PADR + 1;
        int kr = CLAMP ? max(i - PADL, 0)         : i - PADL;
        float4 va = ld4(g_x, ka * NC4 + c4);
        float4 vr = ld4(g_x, kr * NC4 + c4);
        s1 = s1 + va - vr;
        s2 = s2 + va * va - vr * vr;
    }
}

__global__ __launch_bounds__(256) void k_vbox_x()
{
    int c4 = blockIdx.x * 256 + threadIdx.x;
    int r0 = blockIdx.y * SEG_V;
    if (blockIdx.y < 4 || blockIdx.y >= NSEG_V - 4) vbox_x_body<true >(c4, r0);
    else                                            vbox_x_body<false>(c4, r0);
}

// ---------------------------------------------------------------------------
// Row kernel: hbox of (v1,v2) -> mean,mean2 -> A,bb pointwise -> hbox of A,bb.
// One block per row, 512 threads, chunk 9 (coprime with 32 -> conflict-free
// LDS). All window work in smem; outputs staged for coalesced stores.
// ---------------------------------------------------------------------------
__global__ __launch_bounds__(512) void k_hAB()
{
    extern __shared__ float sm[];
    float* sv1 = sm;                 // SMW  (vbox sums of x;   staging out A2)
    float* sv2 = sv1 + SMW;          // SMW  (vbox sums of x^2; staging out bb2)
    float* sA  = sv2 + SMW;          // SMW
    float* sB  = sA + SMW;           // SMW
    int row = blockIdx.x, tid = threadIdx.x;

    const float* r1 = g_t1 + row * NC;
    const float* r2 = g_t2 + row * NC;
    for (int j = tid; j < NC; j += 512) { sv1[PADL + j] = r1[j]; sv2[PADL + j] = r2[j]; }
    if (tid < PADL)             { sv1[tid] = r1[0];           sv2[tid] = r2[0]; }
    else if (tid < PADL + PADR) { sv1[NC + tid] = r1[NC - 1]; sv2[NC + tid] = r2[NC - 1]; }
    __syncthreads();

    int base = tid * HCH;
    int cnt  = (base < NC) ? min(HCH, NC - base) : 0;

    // pass 1: window sums of v1,v2 -> A,bb per column
    if (cnt) {
        float s1 = 0.0f, s2 = 0.0f;
        #pragma unroll 14
        for (int u = 0; u < TAPS; ++u) { s1 += sv1[base + u]; s2 += sv2[base + u]; }
        for (int j = 0; ; ) {
            float mean  = s1 * BOXNORM;
            float mean2 = s2 * BOXNORM;
            float var = mean2 - mean * mean;
            float A = var / (var + 1.0f);       // eps = 1
            sA[PADL + base + j] = A;
            sB[PADL + base + j] = mean - A * mean;
            if (++j >= cnt) break;
            s1 += sv1[base + j + TAPS - 1] - sv1[base + j - 1];
            s2 += sv2[base + j + TAPS - 1] - sv2[base + j - 1];
        }
    }
    __syncthreads();
    if (tid < PADL)             { sA[tid] = sA[PADL];               sB[tid] = sB[PADL]; }
    else if (tid < PADL + PADR) { sA[NC + tid] = sA[PADL + NC - 1]; sB[NC + tid] = sB[PADL + NC - 1]; }
    __syncthreads();

    // pass 2: window sums of A,bb -> staged in sv1,sv2 (dead after pass 1)
    if (cnt) {
        float sa = 0.0f, sb = 0.0f;
        #pragma unroll 14
        for (int u = 0; u < TAPS; ++u) { sa += sA[base + u]; sb += sB[base + u]; }
        sv1[base] = sa; sv2[base] = sb;
        for (int j = 1; j < cnt; ++j) {
            sa += sA[base + j + TAPS - 1] - sA[base + j - 1];
            sb += sB[base + j + TAPS - 1] - sB[base + j - 1];
            sv1[base + j] = sa; sv2[base + j] = sb;
        }
    }
    __syncthreads();
    for (int j = tid; j < NC; j += 512) {
        g_t3[row * NC + j] = sv1[j];
        g_t4[row * NC + j] = sv2[j];
    }
}

// ---------------------------------------------------------------------------
// Final vertical 98-tap of hA,hbb + diff + fused diff-scan prep:
//   diff = A2*x + bb2 ; inc = max(diff[i]-diff[i-1],0)*sp(ww) -> g_t1
//   per-segment partial of inc -> g_pD
// ---------------------------------------------------------------------------
template <bool CLAMP>
__device__ __forceinline__ void vbox_diff_body(
    int c4, int r0, int seg, const float* __restrict__ ww,
    float* __restrict__ o_diff)
{
    int ibeg = CLAMP ? max(r0 - 1, 0) : r0 - 1;
    float4 s1 = f4zero(), s2 = f4zero();
    #pragma unroll 2
    for (int k = ibeg - PADL; k <= ibeg + PADR; ++k) {
        int kc = CLAMP ? min(max(k, 0), M - 1) : k;
        s1 = s1 + ld4(g_t3, kc * NC4 + c4);
        s2 = s2 + ld4(g_t4, kc * NC4 + c4);
    }
    float4 prev = f4zero(), acc = f4zero();
    #pragma unroll 2
    for (int i = ibeg; i < r0 + SEG_V; ++i) {
        int i4 = i * NC4 + c4;
        float4 dv = (BOXNORM * s1) * ld4(g_x, i4) + BOXNORM * s2;
        if (i < r0) {
            prev = dv;                           // warm-up row (r0-1)
        } else {
            if (CLAMP && i == 0) prev = dv;      // prepend: inc[0] = 0
            float4 ic = max4(dv - prev, 0.0f) * sp4(ld4(ww, i4));
            st4(o_diff, i4, dv);
            st4(g_t1, i4, ic);                   // inc plane (t1 reused)
            acc = acc + ic;
            prev = dv;
        }
        int ka = CLAMP ? min(i + PADR + 1, M - 1) : i + PADR + 1;
        int kr = CLAMP ? max(i - PADL, 0)         : i - PADL;
        s1 = s1 + ld4(g_t3, ka * NC4 + c4) - ld4(g_t3, kr * NC4 + c4);
        s2 = s2 + ld4(g_t4, ka * NC4 + c4) - ld4(g_t4, kr * NC4 + c4);
    }
    st4(g_pD, seg * NC4 + c4, acc);
}

__global__ __launch_bounds__(256) void k_vbox_diff(
    const float* __restrict__ ww, float* __restrict__ o_diff)
{
    int c4 = blockIdx.x * 256 + threadIdx.x;
    int seg = blockIdx.y;
    int r0 = seg * SEG_V;
    if (seg < 4 || seg >= NSEG_V - 4) vbox_diff_body<true >(c4, r0, seg, ww, o_diff);
    else                              vbox_diff_body<false>(c4, r0, seg, ww, o_diff);
}

// ---------------------------------------------------------------------------
// Stage 6: diff_adpt = cumsum(inc); b_adpt -= diff_adpt
// ---------------------------------------------------------------------------
__global__ __launch_bounds__(256) void k_dscan(
    float* __restrict__ o_dadpt, float* __restrict__ o_badpt)
{
    int c4  = blockIdx.x * 256 + threadIdx.x;
    int seg = blockIdx.y;
    float4 cum = f4zero();
    #pragma unroll 8
    for (int s = 0; s < seg; ++s) cum = cum + ld4(g_pD, s * NC4 + c4);
    int i0 = seg * SEG_V;
    #pragma unroll 4
    for (int i = i0; i < i0 + SEG_V; ++i) {
        int i4 = i * NC4 + c4;
        cum = cum + ld4(g_t1, i4);
        st4(o_dadpt, i4, cum);
        st4(o_badpt, i4, ld4(o_badpt, i4) - cum);   // finalize b_adpt
    }
}

// ---------------------------------------------------------------------------
extern "C" void kernel_launch(void* const* d_in, const int* in_sizes, int n_in,
                              void* d_out, int out_size)
{
    (void)in_sizes; (void)n_in; (void)out_size;
    const float* b     = (const float*)d_in[0];
    const float* bneg  = (const float*)d_in[1];
    const float* fg    = (const float*)d_in[2];
    const float* hX    = (const float*)d_in[3];
    const float* recon = (const float*)d_in[4];
    const float* fmask = (const float*)d_in[5];
    const float* bold  = (const float*)d_in[6];
    // d_in[7] = r (int32 scalar, value 4; hX stride hardcoded)
    const float* w     = (const float*)d_in[8];
    const float* dcol  = (const float*)d_in[9];
    const float* ww    = (const float*)d_in[10];

    float* out     = (float*)d_out;
    float* o_badpt = out;
    float* o_diff  = out + (size_t)PLANE;
    float* o_dadpt = out + 2 * (size_t)PLANE;
    float* o_b     = out + 3 * (size_t)PLANE;

    // k_hAB needs 4*SMW*4 = 67088 B smem -> dynamic + opt-in
    int hab_smem = 4 * SMW * (int)sizeof(float);
    cudaFuncSetAttribute(k_hAB, cudaFuncAttributeMaxDynamicSharedMemorySize,
                         hab_smem);

    dim3 gC(NC4 / 256, NSEG_C);   // (4, 22)
    dim3 gS(NC4 / 256, NSEG_S);   // (4, 128)
    dim3 gV(NC4 / 256, NSEG_V);   // (4, 128)

    k_decay_part<<<gC, 256>>>(bneg, dcol);
    k_decay_scan<<<gC, 256>>>(bneg, dcol);
    k_b_part    <<<gS, 256>>>(b, w);
    k_main      <<<gS, 256>>>(b, w, fg, hX, recon, fmask, bold, o_badpt, o_b);
    k_vbox_x    <<<gV, 256>>>();
    k_hAB       <<<M, 512, hab_smem>>>();
    k_vbox_diff <<<gV, 256>>>(ww, o_diff);
    k_dscan     <<<gV, 256>>>(o_dadpt, o_badpt);
}